// round 7
// baseline (speedup 1.0000x reference)
#include <cuda_runtime.h>
#include <cuda_fp16.h>
#include <math.h>
#include <stdint.h>

// Problem constants
#define BATCH   8
#define DIM     1024
#define HW      1024
#define NROW    8192
#define NCODE   8192
#define ZQ_ELEMS (BATCH*DIM*HW)
#define OFF_LOSS  ZQ_ELEMS
#define OFF_PERP  (ZQ_ELEMS + 1)
#define OFF_IDX   (ZQ_ELEMS + 2)

#define ESCALE 512.0f
#define MARGIN 1e-3f
#define NTILES 64
#define KSLOT  8

// ---------------- device scratch ---------------------------------------------
__device__ float   g_zflat[(size_t)NROW * DIM];
__device__ __half  g_zh[(size_t)NROW * DIM];
__device__ __half  g_eh[(size_t)NCODE * DIM];
__device__ float   g_S[NROW];
__device__ float   g_T[NCODE];
__device__ unsigned long long g_tmin[(size_t)NROW * NTILES];
__device__ int     g_tcnt[(size_t)NROW * NTILES];
__device__ unsigned long long g_tcand[(size_t)NROW * NTILES * KSLOT];
__device__ int     g_idx[NROW];
__device__ int     g_hist[NCODE];
__device__ double  g_loss;

// ---------------- PTX helpers -------------------------------------------------
__device__ __forceinline__ uint32_t smem_u32(const void* p) {
    uint32_t a;
    asm("{ .reg .u64 t; cvta.to.shared.u64 t, %1; cvt.u32.u64 %0, t; }" : "=r"(a) : "l"(p));
    return a;
}
__device__ __forceinline__ void cp_async16(uint32_t saddr, const void* gptr) {
    asm volatile("cp.async.cg.shared.global [%0], [%1], 16;" :: "r"(saddr), "l"(gptr));
}
__device__ __forceinline__ void cp_commit() { asm volatile("cp.async.commit_group;" ::: "memory"); }
template <int N>
__device__ __forceinline__ void cp_wait() { asm volatile("cp.async.wait_group %0;" :: "n"(N) : "memory"); }

__device__ __forceinline__ void ldsm_x4(uint32_t* r, uint32_t addr) {
    asm volatile("ldmatrix.sync.aligned.m8n8.x4.shared.b16 {%0,%1,%2,%3}, [%4];"
                 : "=r"(r[0]), "=r"(r[1]), "=r"(r[2]), "=r"(r[3]) : "r"(addr));
}
__device__ __forceinline__ void mma16816(float* d, const uint32_t* a, uint32_t b0, uint32_t b1) {
    asm volatile("mma.sync.aligned.m16n8k16.row.col.f32.f16.f16.f32 "
                 "{%0,%1,%2,%3}, {%4,%5,%6,%7}, {%8,%9}, {%0,%1,%2,%3};"
                 : "+f"(d[0]), "+f"(d[1]), "+f"(d[2]), "+f"(d[3])
                 : "r"(a[0]), "r"(a[1]), "r"(a[2]), "r"(a[3]), "r"(b0), "r"(b1));
}
__device__ __forceinline__ unsigned long long packvc(float v, int code) {
    return ((unsigned long long)__float_as_uint(v) << 32) | (unsigned)code;
}
__device__ __forceinline__ float unpackv(unsigned long long p) {
    return __uint_as_float((unsigned)(p >> 32));
}
__device__ __forceinline__ unsigned long long ullmin2(unsigned long long a, unsigned long long b) {
    return (a < b) ? a : b;
}

// ---------------- kernel 0: zero accumulators --------------------------------
__global__ void vq_zero_kernel() {
    int t = blockIdx.x * blockDim.x + threadIdx.x;
    if (t < NCODE) g_hist[t] = 0;
    if (t == 0) g_loss = 0.0;
}

// ---------------- kernel 1: transpose z -> zflat (fp32 + fp16) ---------------
__global__ void vq_transpose_kernel(const float* __restrict__ z) {
    __shared__ float tile[32][33];
    int b = blockIdx.z;
    int hw0 = blockIdx.x * 32;
    int c0  = blockIdx.y * 32;
    const float* src = z + ((size_t)b << 20);
    float* dst = g_zflat + ((size_t)b << 20);
    __half* dsth = g_zh + ((size_t)b << 20);
    #pragma unroll
    for (int r = threadIdx.y; r < 32; r += 8)
        tile[r][threadIdx.x] = src[(size_t)(c0 + r) * HW + hw0 + threadIdx.x];
    __syncthreads();
    #pragma unroll
    for (int r = threadIdx.y; r < 32; r += 8) {
        float v = tile[threadIdx.x][r];
        size_t o = (size_t)(hw0 + r) * DIM + c0 + threadIdx.x;
        dst[o]  = v;
        dsth[o] = __float2half_rn(v);
    }
}

// ---------------- kernel 2: row norms + emb fp16 (scaled) conversion ---------
__global__ void vq_rowsum_kernel(const float* __restrict__ emb) {
    int gw   = (blockIdx.x * blockDim.x + threadIdx.x) >> 5;
    int lane = threadIdx.x & 31;
    if (gw >= NROW + NCODE) return;
    const float* src;
    float* dst;
    bool isEmb = (gw >= NROW);
    if (!isEmb) { src = g_zflat + (size_t)gw * DIM; dst = g_S + gw; }
    else        { src = emb + (size_t)(gw - NROW) * DIM; dst = g_T + (gw - NROW); }
    const float4* s4 = (const float4*)src;
    __half2* eh2 = isEmb ? (__half2*)(g_eh + (size_t)(gw - NROW) * DIM) : nullptr;
    float acc = 0.f;
    #pragma unroll 4
    for (int i = lane; i < DIM / 4; i += 32) {
        float4 v = s4[i];
        if (isEmb) {
            eh2[i * 2]     = __floats2half2_rn(v.x * ESCALE, v.y * ESCALE);
            eh2[i * 2 + 1] = __floats2half2_rn(v.z * ESCALE, v.w * ESCALE);
        }
        acc += v.x * v.x + v.y * v.y + v.z * v.z + v.w * v.w;
    }
    #pragma unroll
    for (int o = 16; o; o >>= 1) acc += __shfl_down_sync(0xffffffffu, acc, o);
    if (lane == 0) *dst = acc;
}

// ---------------- kernel 3: fp16 HMMA GEMM + fused candidate epilogue --------
// CTA: 128 z rows x 128 codes, BK=64, 128 threads (4 warps 2x2, warp 64x64).
// 3 smem buffers, 1-deep prefetch (R3-proven schedule), 2 CTAs/SM.
#define ASTRIDE 144u
#define B_OFF   18432u
#define STAGE_BYTES 36864u
#define MM_SMEM (3u * STAGE_BYTES)      // 110592

__global__ __launch_bounds__(128, 2)
void vq_mm_kernel() {
    extern __shared__ __align__(128) uint8_t smem[];
    const uint32_t sb = smem_u32(smem);
    const int tid = threadIdx.x;
    const int lane = tid & 31, wid = tid >> 5;
    const int warpM = wid >> 1, warpN = wid & 1;     // 2 x 2 warps, warp 64x64
    const int rowBase  = blockIdx.y * 128;
    const int codeBase = blockIdx.x * 128;
    const int tileN = blockIdx.x;

    // loader: each thread loads one A row and one B row per stage (8 cp16 each)
    const __half* gA = g_zh + (size_t)(rowBase + tid) * DIM;
    const __half* gB = g_eh + (size_t)(codeBase + tid) * DIM;
    const uint32_t stA = (uint32_t)tid * ASTRIDE;
    const uint32_t stB = B_OFF + (uint32_t)tid * ASTRIDE;

    // ldmatrix addressing
    const uint32_t a_base = (uint32_t)((warpM * 64 + (lane & 15)) * ASTRIDE + (lane >> 4) * 16);
    const int grp = lane >> 3;
    const uint32_t b_base = B_OFF + (uint32_t)((warpN * 64 + ((grp >> 1) * 8) + (lane & 7)) * ASTRIDE
                                               + (grp & 1) * 16);

    float acc[4][8][4];
    #pragma unroll
    for (int i = 0; i < 4; i++)
        #pragma unroll
        for (int j = 0; j < 8; j++)
            #pragma unroll
            for (int k = 0; k < 4; k++) acc[i][j][k] = 0.f;

    #define ISSUE_STAGE(ktv) do {                                        \
        uint32_t off_ = ((uint32_t)(ktv) % 3u) * STAGE_BYTES;            \
        const __half* ga_ = gA + (ktv) * 64;                             \
        const __half* gb_ = gB + (ktv) * 64;                             \
        _Pragma("unroll")                                                \
        for (int j_ = 0; j_ < 8; j_++)                                   \
            cp_async16(sb + off_ + stA + j_ * 16u, ga_ + j_ * 8);        \
        _Pragma("unroll")                                                \
        for (int j_ = 0; j_ < 8; j_++)                                   \
            cp_async16(sb + off_ + stB + j_ * 16u, gb_ + j_ * 8);        \
    } while (0)

    ISSUE_STAGE(0); cp_commit();
    ISSUE_STAGE(1); cp_commit();

    #pragma unroll 1
    for (int kt = 0; kt < 16; kt++) {
        if (kt < 15) cp_wait<1>(); else cp_wait<0>();
        __syncthreads();
        if (kt <= 13) { ISSUE_STAGE(kt + 2); cp_commit(); }
        const uint32_t stageOff = ((uint32_t)kt % 3u) * STAGE_BYTES;
        const uint32_t As0 = sb + stageOff + a_base;
        const uint32_t Bs0 = sb + stageOff + b_base;
        #pragma unroll
        for (int ks = 0; ks < 4; ks++) {
            uint32_t a[4][4], b[4][4];
            #pragma unroll
            for (int mt = 0; mt < 4; mt++) ldsm_x4(a[mt], As0 + mt * (16u * ASTRIDE) + ks * 32);
            #pragma unroll
            for (int pr = 0; pr < 4; pr++)  ldsm_x4(b[pr], Bs0 + pr * (16u * ASTRIDE) + ks * 32);
            #pragma unroll
            for (int mt = 0; mt < 4; mt++)
                #pragma unroll
                for (int nt = 0; nt < 8; nt++)
                    mma16816(acc[mt][nt], a[mt], b[nt >> 1][(nt & 1) * 2], b[nt >> 1][(nt & 1) * 2 + 1]);
        }
    }
    __syncthreads();
    #undef ISSUE_STAGE

    // ---- fused epilogue: per-row tile min + margin candidates ----
    unsigned long long* sMin = (unsigned long long*)smem;           // 128 * 8B
    int* sCnt = (int*)(smem + 1024);                                // 128 * 4B
    unsigned long long* sCand = (unsigned long long*)(smem + 2048); // 128 * 8 * 8B

    for (int i = tid; i < 128; i += 128) { sMin[i] = ~0ull; sCnt[i] = 0; }
    __syncthreads();

    const float inv2 = 2.0f / ESCALE;
    float Sv[4][2], Tv[8][2];
    #pragma unroll
    for (int mt = 0; mt < 4; mt++) {
        int r0 = rowBase + warpM * 64 + mt * 16 + (lane >> 2);
        Sv[mt][0] = g_S[r0]; Sv[mt][1] = g_S[r0 + 8];
    }
    #pragma unroll
    for (int nt = 0; nt < 8; nt++) {
        int c0 = codeBase + warpN * 64 + nt * 8 + (lane & 3) * 2;
        Tv[nt][0] = g_T[c0]; Tv[nt][1] = g_T[c0 + 1];
    }

    // pass 1: per-row min (quad-lane pre-reduce + shared atomicMin)
    #pragma unroll
    for (int mt = 0; mt < 4; mt++) {
        #pragma unroll
        for (int half = 0; half < 2; half++) {
            unsigned long long pk = ~0ull;
            #pragma unroll
            for (int nt = 0; nt < 8; nt++) {
                int c0 = warpN * 64 + nt * 8 + (lane & 3) * 2;
                #pragma unroll
                for (int j = 0; j < 2; j++) {
                    float v = __fsub_rn(__fadd_rn(Sv[mt][half], Tv[nt][j]),
                                        inv2 * acc[mt][nt][half * 2 + j]);
                    pk = ullmin2(pk, packvc(v, codeBase + c0 + j));
                }
            }
            pk = ullmin2(pk, __shfl_xor_sync(0xffffffffu, pk, 1));
            pk = ullmin2(pk, __shfl_xor_sync(0xffffffffu, pk, 2));
            if ((lane & 3) == 0) {
                int rl = warpM * 64 + mt * 16 + (lane >> 2) + half * 8;
                atomicMin(&sMin[rl], pk);
            }
        }
    }
    __syncthreads();

    // pass 2: append candidates within tileMin + MARGIN
    #pragma unroll
    for (int mt = 0; mt < 4; mt++) {
        #pragma unroll
        for (int half = 0; half < 2; half++) {
            int rl = warpM * 64 + mt * 16 + (lane >> 2) + half * 8;
            float thr = unpackv(sMin[rl]) + MARGIN;
            #pragma unroll
            for (int nt = 0; nt < 8; nt++) {
                int c0 = warpN * 64 + nt * 8 + (lane & 3) * 2;
                #pragma unroll
                for (int j = 0; j < 2; j++) {
                    float v = __fsub_rn(__fadd_rn(Sv[mt][half], Tv[nt][j]),
                                        inv2 * acc[mt][nt][half * 2 + j]);
                    if (v <= thr) {
                        int p = atomicAdd(&sCnt[rl], 1);
                        if (p < KSLOT) sCand[rl * KSLOT + p] = packvc(v, codeBase + c0 + j);
                    }
                }
            }
        }
    }
    __syncthreads();

    // write out
    if (tid < 128) {
        size_t o = (size_t)(rowBase + tid) * NTILES + tileN;
        g_tmin[o] = sMin[tid];
        g_tcnt[o] = sCnt[tid];
    }
    {
        size_t o = ((size_t)(rowBase + tid) * NTILES + tileN) * KSLOT;
        #pragma unroll
        for (int j = 0; j < KSLOT; j++) g_tcand[o + j] = sCand[tid * KSLOT + j];
    }
}

// ---------------- kernel 4: parallel candidate gather + exact fp32 rescore ---
__global__ __launch_bounds__(256, 4)
void vq_scan_kernel(const float* __restrict__ emb, float* __restrict__ out) {
    const int n = blockIdx.x;
    const int t = threadIdx.x;
    const int lane = t & 31, w = t >> 5;

    __shared__ unsigned long long s_tm[NTILES];
    __shared__ int   s_tc[NTILES];
    __shared__ float s_thr;
    __shared__ int   s_cnt;
    __shared__ int   s_codes[512];
    __shared__ int   s_ovf[16];
    __shared__ int   s_novf;
    __shared__ float s_ws[8];
    __shared__ float s_bd;
    __shared__ int   s_bk;

    if (t < NTILES) {
        s_tm[t] = g_tmin[(size_t)n * NTILES + t];
        s_tc[t] = g_tcnt[(size_t)n * NTILES + t];
    }
    if (t == 0) {
        s_cnt = 0; s_novf = 0;
        s_bd = __int_as_float(0x7f800000);
        s_bk = 0x7fffffff;
    }
    __syncthreads();

    if (t < 32) {
        unsigned long long m = ullmin2(s_tm[t], s_tm[t + 32]);
        #pragma unroll
        for (int o = 16; o; o >>= 1) {
            unsigned long long v = __shfl_down_sync(0xffffffffu, m, o);
            m = ullmin2(m, v);
        }
        if (t == 0) s_thr = unpackv(m) + MARGIN;
    }
    __syncthreads();
    const float thr = s_thr;

    if (t < NTILES && unpackv(s_tm[t]) <= thr) {
        int cnt = s_tc[t];
        if (cnt <= KSLOT) {
            size_t base = ((size_t)n * NTILES + t) * KSLOT;
            for (int c = 0; c < cnt; c++) {
                unsigned long long cd = g_tcand[base + c];
                if (unpackv(cd) <= thr) {
                    int p = atomicAdd(&s_cnt, 1);
                    if (p < 512) s_codes[p] = (int)(cd & 0xffffffffu);
                }
            }
        } else {
            int p = atomicAdd(&s_novf, 1);
            if (p < 16) s_ovf[p] = t;
        }
    }
    __syncthreads();
    {
        int novf = s_novf < 16 ? s_novf : 16;
        for (int o = 0; o < novf; o++) {
            if (t < 128) {
                int p = atomicAdd(&s_cnt, 1);
                if (p < 512) s_codes[p] = s_ovf[o] * 128 + t;
            }
        }
    }
    __syncthreads();

    const bool full = (s_cnt > 512) || (s_novf > 16);
    const int total = full ? NCODE : s_cnt;

    const float4 zv = ((const float4*)(g_zflat + (size_t)n * DIM))[t];
    const float S = g_S[n];

    for (int c = 0; c < total; c++) {
        int k = full ? c : s_codes[c];
        float4 ev = ((const float4*)(emb + (size_t)k * DIM))[t];
        float p = fmaf(zv.x, ev.x, fmaf(zv.y, ev.y, fmaf(zv.z, ev.z, zv.w * ev.w)));
        #pragma unroll
        for (int o = 16; o; o >>= 1) p += __shfl_down_sync(0xffffffffu, p, o);
        if (lane == 0) s_ws[w] = p;
        __syncthreads();
        if (t == 0) {
            float P = 0.f;
            #pragma unroll
            for (int i = 0; i < 8; i++) P += s_ws[i];
            float T = g_T[k];
            float d = __fsub_rn(__fadd_rn(S, T), 2.0f * P);
            if (d < s_bd || (d == s_bd && k < s_bk)) { s_bd = d; s_bk = k; }
        }
        __syncthreads();
    }
    if (t == 0) {
        int bk = s_bk;
        g_idx[n] = bk;
        out[OFF_IDX + n] = (float)bk;
        atomicAdd(&g_hist[bk], 1);
    }
}

// ---------------- kernel 5: gather codebook, STE output, loss ----------------
__global__ void vq_gather_kernel(const float* __restrict__ z,
                                 const float* __restrict__ emb,
                                 float* __restrict__ out) {
    int t = blockIdx.x * blockDim.x + threadIdx.x;
    int hw = t & 1023;
    int c  = (t >> 10) & 1023;
    int b  = t >> 20;
    int n  = (b << 10) | hw;
    int code = g_idx[n];
    float zv = z[t];
    float e  = emb[(size_t)code * DIM + c];
    float diff = __fsub_rn(e, zv);
    out[t] = __fadd_rn(zv, diff);
    float sq = diff * diff;
    #pragma unroll
    for (int o = 16; o; o >>= 1) sq += __shfl_down_sync(0xffffffffu, sq, o);
    __shared__ float warpsum[8];
    int lane = threadIdx.x & 31, wid = threadIdx.x >> 5;
    if (lane == 0) warpsum[wid] = sq;
    __syncthreads();
    if (wid == 0) {
        float v = (lane < 8) ? warpsum[lane] : 0.f;
        #pragma unroll
        for (int o = 4; o; o >>= 1) v += __shfl_down_sync(0xffffffffu, v, o);
        if (lane == 0) atomicAdd(&g_loss, (double)v);
    }
}

// ---------------- kernel 6: finalize loss + perplexity -----------------------
__global__ void vq_finalize_kernel(float* __restrict__ out) {
    __shared__ float warpsum[8];
    int tid = threadIdx.x;
    float s = 0.f;
    for (int k = tid; k < NCODE; k += 256) {
        float c = (float)g_hist[k];
        float p = c * (1.0f / (float)NROW);
        s += p * logf(p + 1e-10f);
    }
    #pragma unroll
    for (int o = 16; o; o >>= 1) s += __shfl_down_sync(0xffffffffu, s, o);
    int lane = tid & 31, wid = tid >> 5;
    if (lane == 0) warpsum[wid] = s;
    __syncthreads();
    if (wid == 0) {
        float v = (lane < 8) ? warpsum[lane] : 0.f;
        #pragma unroll
        for (int o = 4; o; o >>= 1) v += __shfl_down_sync(0xffffffffu, v, o);
        if (lane == 0) {
            out[OFF_PERP] = expf(-v);
            double m = g_loss / (double)ZQ_ELEMS;
            float mf = (float)m;
            out[OFF_LOSS] = __fadd_rn(mf, 0.25f * mf);
        }
    }
}

// ---------------- launch ------------------------------------------------------
extern "C" void kernel_launch(void* const* d_in, const int* in_sizes, int n_in,
                              void* d_out, int out_size) {
    const float* z   = (const float*)d_in[0];
    const float* emb = (const float*)d_in[1];
    float* out = (float*)d_out;
    (void)in_sizes; (void)n_in; (void)out_size;

    cudaFuncSetAttribute(vq_mm_kernel, cudaFuncAttributeMaxDynamicSharedMemorySize, MM_SMEM);

    vq_zero_kernel<<<32, 256>>>();

    dim3 tb(32, 8);
    dim3 tg(32, 32, BATCH);
    vq_transpose_kernel<<<tg, tb>>>(z);

    vq_rowsum_kernel<<<(NROW + NCODE) * 32 / 256, 256>>>(emb);

    dim3 mg(NCODE / 128, NROW / 128);
    vq_mm_kernel<<<mg, 128, MM_SMEM>>>();

    vq_scan_kernel<<<NROW, 256>>>(emb, out);

    vq_gather_kernel<<<ZQ_ELEMS / 256, 256>>>(z, emb, out);

    vq_finalize_kernel<<<1, 256>>>(out);
}

// round 8
// speedup vs baseline: 1.2508x; 1.2508x over previous
#include <cuda_runtime.h>
#include <cuda_fp16.h>
#include <math.h>
#include <stdint.h>

// Problem constants
#define BATCH   8
#define DIM     1024
#define HW      1024
#define NROW    8192
#define NCODE   8192
#define ZQ_ELEMS (BATCH*DIM*HW)
#define OFF_LOSS  ZQ_ELEMS
#define OFF_PERP  (ZQ_ELEMS + 1)
#define OFF_IDX   (ZQ_ELEMS + 2)

#define ESCALE 512.0f
#define MARGIN 1e-3f
#define NTILES 64
#define KSLOT  8

// ---------------- device scratch ---------------------------------------------
__device__ float   g_zflat[(size_t)NROW * DIM];
__device__ __half  g_zh[(size_t)NROW * DIM];
__device__ __half  g_eh[(size_t)NCODE * DIM];
__device__ float   g_S[NROW];
__device__ float   g_T[NCODE];
__device__ unsigned long long g_tmin[(size_t)NROW * NTILES];
__device__ int     g_tcnt[(size_t)NROW * NTILES];
__device__ unsigned long long g_tcand[(size_t)NROW * NTILES * KSLOT];
__device__ int     g_idx[NROW];
__device__ int     g_hist[NCODE];
__device__ double  g_loss;

// ---------------- PTX helpers -------------------------------------------------
__device__ __forceinline__ uint32_t smem_u32(const void* p) {
    uint32_t a;
    asm("{ .reg .u64 t; cvta.to.shared.u64 t, %1; cvt.u32.u64 %0, t; }" : "=r"(a) : "l"(p));
    return a;
}
__device__ __forceinline__ void cp_async16(uint32_t saddr, const void* gptr) {
    asm volatile("cp.async.cg.shared.global [%0], [%1], 16;" :: "r"(saddr), "l"(gptr));
}
__device__ __forceinline__ void cp_mbar_arrive(uint32_t mbar) {
    asm volatile("cp.async.mbarrier.arrive.noinc.shared.b64 [%0];" :: "r"(mbar) : "memory");
}
__device__ __forceinline__ void mbar_init(uint32_t a, uint32_t cnt) {
    asm volatile("mbarrier.init.shared.b64 [%0], %1;" :: "r"(a), "r"(cnt) : "memory");
}
__device__ __forceinline__ void mbar_arrive(uint32_t a) {
    asm volatile("mbarrier.arrive.shared.b64 _, [%0];" :: "r"(a) : "memory");
}
// blocks while the barrier's current phase == parity
__device__ __forceinline__ void mbar_wait(uint32_t mbar, uint32_t parity) {
    asm volatile(
        "{\n\t.reg .pred P1;\n\t"
        "WAIT_LOOP_%=:\n\t"
        "mbarrier.try_wait.parity.acquire.cta.shared::cta.b64 P1, [%0], %1, 0x989680;\n\t"
        "@P1 bra.uni WAIT_DONE_%=;\n\t"
        "bra.uni WAIT_LOOP_%=;\n\t"
        "WAIT_DONE_%=:\n\t}"
        :: "r"(mbar), "r"(parity) : "memory");
}
__device__ __forceinline__ void ldsm_x4(uint32_t* r, uint32_t addr) {
    asm volatile("ldmatrix.sync.aligned.m8n8.x4.shared.b16 {%0,%1,%2,%3}, [%4];"
                 : "=r"(r[0]), "=r"(r[1]), "=r"(r[2]), "=r"(r[3]) : "r"(addr));
}
__device__ __forceinline__ void mma16816(float* d, const uint32_t* a, uint32_t b0, uint32_t b1) {
    asm volatile("mma.sync.aligned.m16n8k16.row.col.f32.f16.f16.f32 "
                 "{%0,%1,%2,%3}, {%4,%5,%6,%7}, {%8,%9}, {%0,%1,%2,%3};"
                 : "+f"(d[0]), "+f"(d[1]), "+f"(d[2]), "+f"(d[3])
                 : "r"(a[0]), "r"(a[1]), "r"(a[2]), "r"(a[3]), "r"(b0), "r"(b1));
}
__device__ __forceinline__ unsigned long long packvc(float v, int code) {
    return ((unsigned long long)__float_as_uint(v) << 32) | (unsigned)code;
}
__device__ __forceinline__ float unpackv(unsigned long long p) {
    return __uint_as_float((unsigned)(p >> 32));
}
__device__ __forceinline__ unsigned long long ullmin2(unsigned long long a, unsigned long long b) {
    return (a < b) ? a : b;
}

// ---------------- kernel 0: zero accumulators --------------------------------
__global__ void vq_zero_kernel() {
    int t = blockIdx.x * blockDim.x + threadIdx.x;
    if (t < NCODE) g_hist[t] = 0;
    if (t == 0) g_loss = 0.0;
}

// ---------------- kernel 1: transpose z -> zflat (fp32 + fp16) ---------------
__global__ void vq_transpose_kernel(const float* __restrict__ z) {
    __shared__ float tile[32][33];
    int b = blockIdx.z;
    int hw0 = blockIdx.x * 32;
    int c0  = blockIdx.y * 32;
    const float* src = z + ((size_t)b << 20);
    float* dst = g_zflat + ((size_t)b << 20);
    __half* dsth = g_zh + ((size_t)b << 20);
    #pragma unroll
    for (int r = threadIdx.y; r < 32; r += 8)
        tile[r][threadIdx.x] = src[(size_t)(c0 + r) * HW + hw0 + threadIdx.x];
    __syncthreads();
    #pragma unroll
    for (int r = threadIdx.y; r < 32; r += 8) {
        float v = tile[threadIdx.x][r];
        size_t o = (size_t)(hw0 + r) * DIM + c0 + threadIdx.x;
        dst[o]  = v;
        dsth[o] = __float2half_rn(v);
    }
}

// ---------------- kernel 2: row norms + emb fp16 (scaled) conversion ---------
__global__ void vq_rowsum_kernel(const float* __restrict__ emb) {
    int gw   = (blockIdx.x * blockDim.x + threadIdx.x) >> 5;
    int lane = threadIdx.x & 31;
    if (gw >= NROW + NCODE) return;
    const float* src;
    float* dst;
    bool isEmb = (gw >= NROW);
    if (!isEmb) { src = g_zflat + (size_t)gw * DIM; dst = g_S + gw; }
    else        { src = emb + (size_t)(gw - NROW) * DIM; dst = g_T + (gw - NROW); }
    const float4* s4 = (const float4*)src;
    __half2* eh2 = isEmb ? (__half2*)(g_eh + (size_t)(gw - NROW) * DIM) : nullptr;
    float acc = 0.f;
    #pragma unroll 4
    for (int i = lane; i < DIM / 4; i += 32) {
        float4 v = s4[i];
        if (isEmb) {
            eh2[i * 2]     = __floats2half2_rn(v.x * ESCALE, v.y * ESCALE);
            eh2[i * 2 + 1] = __floats2half2_rn(v.z * ESCALE, v.w * ESCALE);
        }
        acc += v.x * v.x + v.y * v.y + v.z * v.z + v.w * v.w;
    }
    #pragma unroll
    for (int o = 16; o; o >>= 1) acc += __shfl_down_sync(0xffffffffu, acc, o);
    if (lane == 0) *dst = acc;
}

// ---------------- kernel 3: fp16 HMMA GEMM, mbarrier free-running pipeline ---
// CTA: 128 z rows x 128 codes, BK=32, 256 threads (8 warps 2x4, warp 64x32).
// 4 stages; full[] = cp.async completion (count 256); empty[] = per-warp
// arrive right after LDSM (count 8). No __syncthreads in the K loop.
#define ASTRIDE 80u
#define STAGE_BYTES 20480u
#define AS_OFF(s) ((uint32_t)(s) * STAGE_BYTES)
#define BS_OFF(s) ((uint32_t)(s) * STAGE_BYTES + 10240u)
#define MM_SMEM (4u * STAGE_BYTES)     // 81920
#define NITER 32

__global__ __launch_bounds__(256, 2)
void vq_mm_kernel() {
    extern __shared__ __align__(128) uint8_t smem[];
    __shared__ __align__(8) uint64_t s_bars[8];   // full[0..3], empty[0..3]
    const uint32_t sb = smem_u32(smem);
    const int tid = threadIdx.x;
    const int lane = tid & 31, wid = tid >> 5;
    const int warpM = wid >> 2, warpN = wid & 3;
    const int rowBase  = blockIdx.y * 128;
    const int codeBase = blockIdx.x * 128;
    const int tileN = blockIdx.x;

    uint32_t full_b[4], empty_b[4];
    #pragma unroll
    for (int s = 0; s < 4; s++) {
        full_b[s]  = smem_u32(&s_bars[s]);
        empty_b[s] = smem_u32(&s_bars[4 + s]);
    }
    if (tid == 0) {
        #pragma unroll
        for (int s = 0; s < 4; s++) { mbar_init(full_b[s], 256); mbar_init(empty_b[s], 8); }
    }
    __syncthreads();

    // loader addressing (R3 geometry)
    const int ldrow = tid >> 1;
    const int ldc0  = (tid & 1) * 2;
    const __half* gA = g_zh + (size_t)(rowBase + ldrow) * DIM + ldc0 * 8;
    const __half* gB = g_eh + (size_t)(codeBase + ldrow) * DIM + ldc0 * 8;
    const uint32_t stA = (uint32_t)ldrow * ASTRIDE + (uint32_t)ldc0 * 16u;

    // ldmatrix addressing
    const uint32_t a_base = (uint32_t)((warpM * 64 + (lane & 15)) * ASTRIDE + (lane >> 4) * 16);
    const int grp = lane >> 3;
    const uint32_t b_base = (uint32_t)((warpN * 32 + ((grp >> 1) * 8) + (lane & 7)) * ASTRIDE
                                       + (grp & 1) * 16);

    float acc[4][4][4];
    #pragma unroll
    for (int i = 0; i < 4; i++)
        #pragma unroll
        for (int j = 0; j < 4; j++)
            #pragma unroll
            for (int k = 0; k < 4; k++) acc[i][j][k] = 0.f;

    #define ISSUE_STAGE(v) do {                                     \
        uint32_t s_ = (uint32_t)(v) & 3u;                           \
        int k0_ = (v) * 32;                                         \
        uint32_t a0_ = sb + AS_OFF(s_) + stA;                       \
        cp_async16(a0_,      gA + k0_);                             \
        cp_async16(a0_ + 16, gA + k0_ + 8);                         \
        uint32_t b0_ = sb + BS_OFF(s_) + stA;                       \
        cp_async16(b0_,      gB + k0_);                             \
        cp_async16(b0_ + 16, gB + k0_ + 8);                         \
        cp_mbar_arrive(full_b[s_]);                                 \
    } while (0)

    // prologue: fill stages 0..2 (first fills: no empty wait needed)
    ISSUE_STAGE(0);
    ISSUE_STAGE(1);
    ISSUE_STAGE(2);

    #pragma unroll 1
    for (int it = 0; it < NITER; it++) {
        const int v = it + 3;                  // stage slot being refilled
        if (v < NITER) {
            uint32_t sv = (uint32_t)v & 3u;
            // fill index f = v>>2; f>=1 here iff v>=4; wait empty (parity (f+1)&1)
            if (v >= 4) mbar_wait(empty_b[sv], (uint32_t)(((v >> 2) + 1) & 1));
            ISSUE_STAGE(v);
        }
        const uint32_t s = (uint32_t)it & 3u;
        mbar_wait(full_b[s], (uint32_t)((it >> 2) & 1));

        const uint32_t As0 = sb + AS_OFF(s) + a_base;
        const uint32_t Bs0 = sb + BS_OFF(s) + b_base;

        uint32_t a0[4][4], b0[2][4], a1[4][4], b1[2][4];
        #pragma unroll
        for (int mt = 0; mt < 4; mt++) ldsm_x4(a0[mt], As0 + mt * (16u * ASTRIDE));
        #pragma unroll
        for (int pr = 0; pr < 2; pr++)  ldsm_x4(b0[pr], Bs0 + pr * (16u * ASTRIDE));
        #pragma unroll
        for (int mt = 0; mt < 4; mt++)
            #pragma unroll
            for (int nt = 0; nt < 4; nt++)
                mma16816(acc[mt][nt], a0[mt], b0[nt >> 1][(nt & 1) * 2], b0[nt >> 1][(nt & 1) * 2 + 1]);

        #pragma unroll
        for (int mt = 0; mt < 4; mt++) ldsm_x4(a1[mt], As0 + mt * (16u * ASTRIDE) + 32u);
        #pragma unroll
        for (int pr = 0; pr < 2; pr++)  ldsm_x4(b1[pr], Bs0 + pr * (16u * ASTRIDE) + 32u);
        __syncwarp();
        if (lane == 0) mbar_arrive(empty_b[s]);   // buffer free for refill
        #pragma unroll
        for (int mt = 0; mt < 4; mt++)
            #pragma unroll
            for (int nt = 0; nt < 4; nt++)
                mma16816(acc[mt][nt], a1[mt], b1[nt >> 1][(nt & 1) * 2], b1[nt >> 1][(nt & 1) * 2 + 1]);
    }
    __syncthreads();
    #undef ISSUE_STAGE

    // ---- fused epilogue: per-row tile min + margin candidates ----
    unsigned long long* sMin = (unsigned long long*)smem;           // 128 * 8B
    int* sCnt = (int*)(smem + 1024);                                // 128 * 4B
    unsigned long long* sCand = (unsigned long long*)(smem + 2048); // 128 * 8 * 8B

    for (int i = tid; i < 128; i += 256) { sMin[i] = ~0ull; sCnt[i] = 0; }
    __syncthreads();

    const float inv2 = 2.0f / ESCALE;
    float Sv[4][2], Tv[4][2];
    #pragma unroll
    for (int mt = 0; mt < 4; mt++) {
        int r0 = rowBase + warpM * 64 + mt * 16 + (lane >> 2);
        Sv[mt][0] = g_S[r0]; Sv[mt][1] = g_S[r0 + 8];
    }
    #pragma unroll
    for (int nt = 0; nt < 4; nt++) {
        int c0 = codeBase + warpN * 32 + nt * 8 + (lane & 3) * 2;
        Tv[nt][0] = g_T[c0]; Tv[nt][1] = g_T[c0 + 1];
    }

    // pass 1: per-row min (quad-lane pre-reduce + shared atomicMin)
    #pragma unroll
    for (int mt = 0; mt < 4; mt++) {
        #pragma unroll
        for (int half = 0; half < 2; half++) {
            unsigned long long pk = ~0ull;
            #pragma unroll
            for (int nt = 0; nt < 4; nt++) {
                int c0 = warpN * 32 + nt * 8 + (lane & 3) * 2;
                #pragma unroll
                for (int j = 0; j < 2; j++) {
                    float v = __fsub_rn(__fadd_rn(Sv[mt][half], Tv[nt][j]),
                                        inv2 * acc[mt][nt][half * 2 + j]);
                    pk = ullmin2(pk, packvc(v, codeBase + c0 + j));
                }
            }
            pk = ullmin2(pk, __shfl_xor_sync(0xffffffffu, pk, 1));
            pk = ullmin2(pk, __shfl_xor_sync(0xffffffffu, pk, 2));
            if ((lane & 3) == 0) {
                int rl = warpM * 64 + mt * 16 + (lane >> 2) + half * 8;
                atomicMin(&sMin[rl], pk);
            }
        }
    }
    __syncthreads();

    // pass 2: append candidates within tileMin + MARGIN
    #pragma unroll
    for (int mt = 0; mt < 4; mt++) {
        #pragma unroll
        for (int half = 0; half < 2; half++) {
            int rl = warpM * 64 + mt * 16 + (lane >> 2) + half * 8;
            float thr = unpackv(sMin[rl]) + MARGIN;
            #pragma unroll
            for (int nt = 0; nt < 4; nt++) {
                int c0 = warpN * 32 + nt * 8 + (lane & 3) * 2;
                #pragma unroll
                for (int j = 0; j < 2; j++) {
                    float v = __fsub_rn(__fadd_rn(Sv[mt][half], Tv[nt][j]),
                                        inv2 * acc[mt][nt][half * 2 + j]);
                    if (v <= thr) {
                        int p = atomicAdd(&sCnt[rl], 1);
                        if (p < KSLOT) sCand[rl * KSLOT + p] = packvc(v, codeBase + c0 + j);
                    }
                }
            }
        }
    }
    __syncthreads();

    // write out
    if (tid < 128) {
        size_t o = (size_t)(rowBase + tid) * NTILES + tileN;
        g_tmin[o] = sMin[tid];
        g_tcnt[o] = sCnt[tid];
    }
    {
        int row = tid >> 1, h = (tid & 1) * 4;
        size_t o = ((size_t)(rowBase + row) * NTILES + tileN) * KSLOT + h;
        #pragma unroll
        for (int j = 0; j < 4; j++) g_tcand[o + j] = sCand[row * KSLOT + h + j];
    }
}

// ---------------- kernel 4: parallel candidate gather + exact fp32 rescore ---
__global__ __launch_bounds__(256, 4)
void vq_scan_kernel(const float* __restrict__ emb, float* __restrict__ out) {
    const int n = blockIdx.x;
    const int t = threadIdx.x;
    const int lane = t & 31, w = t >> 5;

    __shared__ unsigned long long s_tm[NTILES];
    __shared__ int   s_tc[NTILES];
    __shared__ float s_thr;
    __shared__ int   s_cnt;
    __shared__ int   s_codes[512];
    __shared__ int   s_ovf[16];
    __shared__ int   s_novf;
    __shared__ float s_ws[8];
    __shared__ float s_bd;
    __shared__ int   s_bk;

    if (t < NTILES) {
        s_tm[t] = g_tmin[(size_t)n * NTILES + t];
        s_tc[t] = g_tcnt[(size_t)n * NTILES + t];
    }
    if (t == 0) {
        s_cnt = 0; s_novf = 0;
        s_bd = __int_as_float(0x7f800000);
        s_bk = 0x7fffffff;
    }
    __syncthreads();

    if (t < 32) {
        unsigned long long m = ullmin2(s_tm[t], s_tm[t + 32]);
        #pragma unroll
        for (int o = 16; o; o >>= 1) {
            unsigned long long v = __shfl_down_sync(0xffffffffu, m, o);
            m = ullmin2(m, v);
        }
        if (t == 0) s_thr = unpackv(m) + MARGIN;
    }
    __syncthreads();
    const float thr = s_thr;

    if (t < NTILES && unpackv(s_tm[t]) <= thr) {
        int cnt = s_tc[t];
        if (cnt <= KSLOT) {
            size_t base = ((size_t)n * NTILES + t) * KSLOT;
            for (int c = 0; c < cnt; c++) {
                unsigned long long cd = g_tcand[base + c];
                if (unpackv(cd) <= thr) {
                    int p = atomicAdd(&s_cnt, 1);
                    if (p < 512) s_codes[p] = (int)(cd & 0xffffffffu);
                }
            }
        } else {
            int p = atomicAdd(&s_novf, 1);
            if (p < 16) s_ovf[p] = t;
        }
    }
    __syncthreads();
    {
        int novf = s_novf < 16 ? s_novf : 16;
        for (int o = 0; o < novf; o++) {
            if (t < 128) {
                int p = atomicAdd(&s_cnt, 1);
                if (p < 512) s_codes[p] = s_ovf[o] * 128 + t;
            }
        }
    }
    __syncthreads();

    const bool full = (s_cnt > 512) || (s_novf > 16);
    const int total = full ? NCODE : s_cnt;

    const float4 zv = ((const float4*)(g_zflat + (size_t)n * DIM))[t];
    const float S = g_S[n];

    for (int c = 0; c < total; c++) {
        int k = full ? c : s_codes[c];
        float4 ev = ((const float4*)(emb + (size_t)k * DIM))[t];
        float p = fmaf(zv.x, ev.x, fmaf(zv.y, ev.y, fmaf(zv.z, ev.z, zv.w * ev.w)));
        #pragma unroll
        for (int o = 16; o; o >>= 1) p += __shfl_down_sync(0xffffffffu, p, o);
        if (lane == 0) s_ws[w] = p;
        __syncthreads();
        if (t == 0) {
            float P = 0.f;
            #pragma unroll
            for (int i = 0; i < 8; i++) P += s_ws[i];
            float T = g_T[k];
            float d = __fsub_rn(__fadd_rn(S, T), 2.0f * P);
            if (d < s_bd || (d == s_bd && k < s_bk)) { s_bd = d; s_bk = k; }
        }
        __syncthreads();
    }
    if (t == 0) {
        int bk = s_bk;
        g_idx[n] = bk;
        out[OFF_IDX + n] = (float)bk;
        atomicAdd(&g_hist[bk], 1);
    }
}

// ---------------- kernel 5: gather codebook, STE output, loss ----------------
__global__ void vq_gather_kernel(const float* __restrict__ z,
                                 const float* __restrict__ emb,
                                 float* __restrict__ out) {
    int t = blockIdx.x * blockDim.x + threadIdx.x;
    int hw = t & 1023;
    int c  = (t >> 10) & 1023;
    int b  = t >> 20;
    int n  = (b << 10) | hw;
    int code = g_idx[n];
    float zv = z[t];
    float e  = emb[(size_t)code * DIM + c];
    float diff = __fsub_rn(e, zv);
    out[t] = __fadd_rn(zv, diff);
    float sq = diff * diff;
    #pragma unroll
    for (int o = 16; o; o >>= 1) sq += __shfl_down_sync(0xffffffffu, sq, o);
    __shared__ float warpsum[8];
    int lane = threadIdx.x & 31, wid = threadIdx.x >> 5;
    if (lane == 0) warpsum[wid] = sq;
    __syncthreads();
    if (wid == 0) {
        float v = (lane < 8) ? warpsum[lane] : 0.f;
        #pragma unroll
        for (int o = 4; o; o >>= 1) v += __shfl_down_sync(0xffffffffu, v, o);
        if (lane == 0) atomicAdd(&g_loss, (double)v);
    }
}

// ---------------- kernel 6: finalize loss + perplexity -----------------------
__global__ void vq_finalize_kernel(float* __restrict__ out) {
    __shared__ float warpsum[8];
    int tid = threadIdx.x;
    float s = 0.f;
    for (int k = tid; k < NCODE; k += 256) {
        float c = (float)g_hist[k];
        float p = c * (1.0f / (float)NROW);
        s += p * logf(p + 1e-10f);
    }
    #pragma unroll
    for (int o = 16; o; o >>= 1) s += __shfl_down_sync(0xffffffffu, s, o);
    int lane = tid & 31, wid = tid >> 5;
    if (lane == 0) warpsum[wid] = s;
    __syncthreads();
    if (wid == 0) {
        float v = (lane < 8) ? warpsum[lane] : 0.f;
        #pragma unroll
        for (int o = 4; o; o >>= 1) v += __shfl_down_sync(0xffffffffu, v, o);
        if (lane == 0) {
            out[OFF_PERP] = expf(-v);
            double m = g_loss / (double)ZQ_ELEMS;
            float mf = (float)m;
            out[OFF_LOSS] = __fadd_rn(mf, 0.25f * mf);
        }
    }
}

// ---------------- launch ------------------------------------------------------
extern "C" void kernel_launch(void* const* d_in, const int* in_sizes, int n_in,
                              void* d_out, int out_size) {
    const float* z   = (const float*)d_in[0];
    const float* emb = (const float*)d_in[1];
    float* out = (float*)d_out;
    (void)in_sizes; (void)n_in; (void)out_size;

    cudaFuncSetAttribute(vq_mm_kernel, cudaFuncAttributeMaxDynamicSharedMemorySize, MM_SMEM);

    vq_zero_kernel<<<32, 256>>>();

    dim3 tb(32, 8);
    dim3 tg(32, 32, BATCH);
    vq_transpose_kernel<<<tg, tb>>>(z);

    vq_rowsum_kernel<<<(NROW + NCODE) * 32 / 256, 256>>>(emb);

    dim3 mg(NCODE / 128, NROW / 128);
    vq_mm_kernel<<<mg, 256, MM_SMEM>>>();

    vq_scan_kernel<<<NROW, 256>>>(emb, out);

    vq_gather_kernel<<<ZQ_ELEMS / 256, 256>>>(z, emb, out);

    vq_finalize_kernel<<<1, 256>>>(out);
}